// round 2
// baseline (speedup 1.0000x reference)
#include <cuda_runtime.h>
#include <math.h>

#define B_  8
#define N_  4096
#define D_  1024
#define H_  16
#define DH_ 64
#define M_  (B_ * N_)   // 32768 rows

// ---------------- scratch (static device memory; allocation-free) ----------
__device__ float g_Q[(size_t)M_ * D_];       // 134 MB
__device__ float g_K[(size_t)M_ * D_];       // 134 MB
__device__ float g_V[(size_t)M_ * D_];       // 134 MB
__device__ float g_O[(size_t)M_ * D_];       // 134 MB
__device__ float g_qnorm[B_ * D_];           // per (b, column) sum of squares
__device__ float g_kv[B_ * H_ * DH_ * DH_];  // (b,h,64,64)

// ---------------------------------------------------------------------------
// GEMM: C[M,1024] = A[M,1024] @ W[1024,1024]^T + bias, with epilogue:
//   MODE 0: none (V projection, final output projection)
//   MODE 1: x -> 1 + elu(x)                     (Q projection)
//   MODE 2: x -> 1 + elu(x); zero row if mask   (K projection)
// 128x128 block tile, BK=8, 256 threads, 8x8 per thread, float4 everywhere.
// ---------------------------------------------------------------------------
template <int MODE>
__global__ void __launch_bounds__(256, 2)
gemm_kernel(const float* __restrict__ A, const float* __restrict__ W,
            const float* __restrict__ bias, const int* __restrict__ mask,
            float* __restrict__ C)
{
    __shared__ __align__(16) float As[8][132];   // padded: conflict-free T-stores
    __shared__ __align__(16) float Bs[8][132];

    const int tid  = threadIdx.x;
    const int bm   = blockIdx.y << 7;
    const int bn   = blockIdx.x << 7;
    const int lrow = tid >> 1;          // 0..127
    const int lk   = (tid & 1) << 2;    // 0 or 4
    const int tm   = (tid >> 4) << 3;   // 0..120
    const int tn   = (tid & 15) << 3;   // 0..120

    const float* Ap = A + (size_t)(bm + lrow) * D_ + lk;
    const float* Wp = W + (size_t)(bn + lrow) * D_ + lk;

    float acc[8][8];
#pragma unroll
    for (int i = 0; i < 8; i++)
#pragma unroll
        for (int j = 0; j < 8; j++) acc[i][j] = 0.f;

    for (int k0 = 0; k0 < D_; k0 += 8) {
        float4 a4 = *(const float4*)(Ap + k0);
        float4 w4 = *(const float4*)(Wp + k0);
        __syncthreads();
        As[lk + 0][lrow] = a4.x; As[lk + 1][lrow] = a4.y;
        As[lk + 2][lrow] = a4.z; As[lk + 3][lrow] = a4.w;
        Bs[lk + 0][lrow] = w4.x; Bs[lk + 1][lrow] = w4.y;
        Bs[lk + 2][lrow] = w4.z; Bs[lk + 3][lrow] = w4.w;
        __syncthreads();
#pragma unroll
        for (int kk = 0; kk < 8; kk++) {
            float ar[8], br[8];
            *(float4*)(ar)     = *(const float4*)(&As[kk][tm]);
            *(float4*)(ar + 4) = *(const float4*)(&As[kk][tm + 4]);
            *(float4*)(br)     = *(const float4*)(&Bs[kk][tn]);
            *(float4*)(br + 4) = *(const float4*)(&Bs[kk][tn + 4]);
#pragma unroll
            for (int i = 0; i < 8; i++)
#pragma unroll
                for (int j = 0; j < 8; j++)
                    acc[i][j] = fmaf(ar[i], br[j], acc[i][j]);
        }
    }

    float bvv[8];
#pragma unroll
    for (int j = 0; j < 8; j++) bvv[j] = bias[bn + tn + j];

#pragma unroll
    for (int i = 0; i < 8; i++) {
        const int row = bm + tm + i;
        float vals[8];
#pragma unroll
        for (int j = 0; j < 8; j++) {
            float x = acc[i][j] + bvv[j];
            if (MODE >= 1) x = (x > 0.f) ? (x + 1.f) : expf(x);  // 1 + elu
            vals[j] = x;
        }
        if (MODE == 2) {
            if (mask[row] != 0) {
#pragma unroll
                for (int j = 0; j < 8; j++) vals[j] = 0.f;
            }
        }
        float* cp = C + (size_t)row * D_ + bn + tn;
        *(float4*)(cp)     = make_float4(vals[0], vals[1], vals[2], vals[3]);
        *(float4*)(cp + 4) = make_float4(vals[4], vals[5], vals[6], vals[7]);
    }
}

// ---------------------------------------------------------------------------
// q normalization over the SEQUENCE axis: per (b, column c in [0,1024)),
// norm over n=4096. Pass A: zero accumulators. Pass B: partial sum-of-squares
// with atomics. Pass C: scale.
// ---------------------------------------------------------------------------
__global__ void zero_qnorm_kernel()
{
    int i = blockIdx.x * 256 + threadIdx.x;
    if (i < B_ * D_) g_qnorm[i] = 0.f;
}

__global__ void __launch_bounds__(256) qcolsumsq_kernel()
{
    // grid (4, 16, 8): x = column tile of 256, y = n-chunk of 256, z = batch
    const int c  = blockIdx.x * 256 + threadIdx.x;
    const int b  = blockIdx.z;
    const int n0 = blockIdx.y * 256;
    const float* p = g_Q + ((size_t)(b * N_ + n0)) * D_ + c;
    float s = 0.f;
#pragma unroll 8
    for (int j = 0; j < 256; j++) {
        float v = p[(size_t)j * D_];
        s = fmaf(v, v, s);
    }
    atomicAdd(&g_qnorm[b * D_ + c], s);
}

__global__ void __launch_bounds__(256) qscale_kernel()
{
    // 8388608 float4s total; grid 32768 x 256
    const int idx = blockIdx.x * 256 + threadIdx.x;       // float4 index
    const int c4  = (idx & 255) << 2;                     // column (mult of 4)
    const int b   = idx >> 20;                            // 4096*256 f4 per batch
    float4 v  = ((const float4*)g_Q)[idx];
    float4 nv = *(const float4*)&g_qnorm[b * D_ + c4];
    v.x /= fmaxf(sqrtf(nv.x), 1e-12f);
    v.y /= fmaxf(sqrtf(nv.y), 1e-12f);
    v.z /= fmaxf(sqrtf(nv.z), 1e-12f);
    v.w /= fmaxf(sqrtf(nv.w), 1e-12f);
    ((float4*)g_Q)[idx] = v;
}

// ---------------------------------------------------------------------------
// k normalization over the FEATURE axis: contiguous 64-float head rows.
// 16 lanes per row, one float4 per lane, shuffle reduce.
// ---------------------------------------------------------------------------
__global__ void __launch_bounds__(256) knorm_kernel()
{
    const int row = blockIdx.x * 16 + (threadIdx.x >> 4);  // 0..524287
    const int l   = threadIdx.x & 15;
    float* p = g_K + (size_t)row * DH_ + l * 4;
    float4 v = *(const float4*)p;
    float s = v.x * v.x + v.y * v.y + v.z * v.z + v.w * v.w;
    s += __shfl_xor_sync(0xffffffffu, s, 1);
    s += __shfl_xor_sync(0xffffffffu, s, 2);
    s += __shfl_xor_sync(0xffffffffu, s, 4);
    s += __shfl_xor_sync(0xffffffffu, s, 8);
    const float inv = 1.0f / fmaxf(sqrtf(s), 1e-12f);
    v.x *= inv; v.y *= inv; v.z *= inv; v.w *= inv;
    *(float4*)p = v;
}

// ---------------------------------------------------------------------------
// kv[b,h,d,e] = sum_n k[b,n,h*64+d] * v[b,n,h*64+e].  One block per (b,h).
// 64x64 output, K=4096, smem-tiled, 4x4 per thread.
// ---------------------------------------------------------------------------
__global__ void __launch_bounds__(256) kv_kernel()
{
    __shared__ __align__(16) float Ks[64][64];
    __shared__ __align__(16) float Vs[64][64];
    const int tid = threadIdx.x;
    const int bh  = blockIdx.x;             // 0..127
    const int b   = bh >> 4, h = bh & 15;
    const size_t base = (size_t)b * N_ * D_ + (size_t)h * DH_;
    const int d0 = (tid & 15) << 2;
    const int e0 = (tid >> 4) << 2;

    float acc[4][4];
#pragma unroll
    for (int i = 0; i < 4; i++)
#pragma unroll
        for (int j = 0; j < 4; j++) acc[i][j] = 0.f;

    for (int n0 = 0; n0 < N_; n0 += 64) {
        __syncthreads();
#pragma unroll
        for (int it = 0; it < 4; it++) {
            int rj = (it << 4) + (tid >> 4);
            int q  = (tid & 15) << 2;
            size_t g = base + (size_t)(n0 + rj) * D_ + q;
            *(float4*)&Ks[rj][q] = *(const float4*)(g_K + g);
            *(float4*)&Vs[rj][q] = *(const float4*)(g_V + g);
        }
        __syncthreads();
#pragma unroll 8
        for (int j = 0; j < 64; j++) {
            float4 kd = *(const float4*)&Ks[j][d0];
            float4 ve = *(const float4*)&Vs[j][e0];
            float kda[4] = {kd.x, kd.y, kd.z, kd.w};
            float vea[4] = {ve.x, ve.y, ve.z, ve.w};
#pragma unroll
            for (int di = 0; di < 4; di++)
#pragma unroll
                for (int ei = 0; ei < 4; ei++)
                    acc[di][ei] = fmaf(kda[di], vea[ei], acc[di][ei]);
        }
    }

    float* outp = g_kv + (size_t)bh * (DH_ * DH_);
#pragma unroll
    for (int di = 0; di < 4; di++)
        *(float4*)&outp[(d0 + di) * DH_ + e0] =
            make_float4(acc[di][0], acc[di][1], acc[di][2], acc[di][3]);
}

// ---------------------------------------------------------------------------
// out[b,n,h*64+e] = sum_d q[b,n,h*64+d] * kv[b,h,d,e].
// Block = (n-tile of 128, h, b). kv tile (64x64) + q tile (128x64) in smem.
// 8 rows x 4 cols per thread.
// ---------------------------------------------------------------------------
__global__ void __launch_bounds__(256) attn_out_kernel()
{
    __shared__ __align__(16) float Qs[128][64];   // 32 KB
    __shared__ __align__(16) float Kvs[64][64];   // 16 KB
    const int tid = threadIdx.x;
    const int b = blockIdx.z, h = blockIdx.y;
    const int n0 = blockIdx.x << 7;
    const size_t qbase = ((size_t)b * N_ + n0) * D_ + (size_t)h * DH_;
    const float* kvp = g_kv + (size_t)(b * H_ + h) * (DH_ * DH_);

#pragma unroll
    for (int it = 0; it < 4; it++) {
        int f = (it << 8) + tid;
        ((float4*)&Kvs[0][0])[f] = ((const float4*)kvp)[f];
    }
#pragma unroll
    for (int it = 0; it < 8; it++) {
        int f = (it << 8) + tid;
        int r = f >> 4, q = (f & 15) << 2;
        *(float4*)&Qs[r][q] = *(const float4*)(g_Q + qbase + (size_t)r * D_ + q);
    }
    __syncthreads();

    const int row0 = (tid >> 4) << 3;
    const int col0 = (tid & 15) << 2;
    float4 acc[8];
#pragma unroll
    for (int i = 0; i < 8; i++) acc[i] = make_float4(0.f, 0.f, 0.f, 0.f);

#pragma unroll 4
    for (int d = 0; d < 64; d += 4) {
        float4 k0v = *(const float4*)&Kvs[d + 0][col0];
        float4 k1v = *(const float4*)&Kvs[d + 1][col0];
        float4 k2v = *(const float4*)&Kvs[d + 2][col0];
        float4 k3v = *(const float4*)&Kvs[d + 3][col0];
#pragma unroll
        for (int i = 0; i < 8; i++) {
            float4 q4 = *(const float4*)&Qs[row0 + i][d];
            acc[i].x = fmaf(q4.x, k0v.x, acc[i].x);
            acc[i].y = fmaf(q4.x, k0v.y, acc[i].y);
            acc[i].z = fmaf(q4.x, k0v.z, acc[i].z);
            acc[i].w = fmaf(q4.x, k0v.w, acc[i].w);
            acc[i].x = fmaf(q4.y, k1v.x, acc[i].x);
            acc[i].y = fmaf(q4.y, k1v.y, acc[i].y);
            acc[i].z = fmaf(q4.y, k1v.z, acc[i].z);
            acc[i].w = fmaf(q4.y, k1v.w, acc[i].w);
            acc[i].x = fmaf(q4.z, k2v.x, acc[i].x);
            acc[i].y = fmaf(q4.z, k2v.y, acc[i].y);
            acc[i].z = fmaf(q4.z, k2v.z, acc[i].z);
            acc[i].w = fmaf(q4.z, k2v.w, acc[i].w);
            acc[i].x = fmaf(q4.w, k3v.x, acc[i].x);
            acc[i].y = fmaf(q4.w, k3v.y, acc[i].y);
            acc[i].z = fmaf(q4.w, k3v.z, acc[i].z);
            acc[i].w = fmaf(q4.w, k3v.w, acc[i].w);
        }
    }

#pragma unroll
    for (int i = 0; i < 8; i++)
        *(float4*)(g_O + qbase + (size_t)(row0 + i) * D_ + col0) = acc[i];
}

// ---------------------------------------------------------------------------
extern "C" void kernel_launch(void* const* d_in, const int* in_sizes, int n_in,
                              void* d_out, int out_size)
{
    (void)in_sizes; (void)n_in; (void)out_size;
    const float* query = (const float*)d_in[0];
    const float* key   = (const float*)d_in[1];
    const float* value = (const float*)d_in[2];
    const int*   mask  = (const int*)d_in[3];   // bool materialized as int32
    const float* Wq = (const float*)d_in[4];
    const float* bq = (const float*)d_in[5];
    const float* Wk = (const float*)d_in[6];
    const float* bk = (const float*)d_in[7];
    const float* Wv = (const float*)d_in[8];
    const float* bv = (const float*)d_in[9];
    const float* Wo = (const float*)d_in[10];
    const float* bo = (const float*)d_in[11];
    float* out = (float*)d_out;

    float *Q = nullptr, *K = nullptr, *V = nullptr, *O = nullptr;
    cudaGetSymbolAddress((void**)&Q, g_Q);
    cudaGetSymbolAddress((void**)&K, g_K);
    cudaGetSymbolAddress((void**)&V, g_V);
    cudaGetSymbolAddress((void**)&O, g_O);

    dim3 gblk(256);
    dim3 ggrid(D_ / 128, M_ / 128);   // (8, 256)

    gemm_kernel<1><<<ggrid, gblk>>>(query, Wq, bq, nullptr, Q);
    gemm_kernel<2><<<ggrid, gblk>>>(key,   Wk, bk, mask,    K);
    gemm_kernel<0><<<ggrid, gblk>>>(value, Wv, bv, nullptr, V);

    zero_qnorm_kernel<<<(B_ * D_ + 255) / 256, 256>>>();
    qcolsumsq_kernel<<<dim3(4, 16, 8), 256>>>();
    qscale_kernel<<<(M_ * D_ / 4) / 256, 256>>>();   // 32768 blocks
    knorm_kernel<<<(M_ * H_) / 16, 256>>>();         // 32768 blocks

    kv_kernel<<<B_ * H_, 256>>>();                   // 128 blocks
    attn_out_kernel<<<dim3(N_ / 128, H_, B_), 256>>>();

    gemm_kernel<0><<<ggrid, gblk>>>(O, Wo, bo, nullptr, out);
}

// round 4
// speedup vs baseline: 2.4137x; 2.4137x over previous
#include <cuda_runtime.h>
#include <cuda_bf16.h>
#include <math.h>
#include <stdint.h>

#define B_  8
#define N_  4096
#define D_  1024
#define H_  16
#define DH_ 64
#define M_  (B_ * N_)   // 32768 rows

// ---------------- scratch (static device memory; allocation-free) ----------
__device__ float g_Q[(size_t)M_ * D_];
__device__ float g_K[(size_t)M_ * D_];
__device__ float g_V[(size_t)M_ * D_];
__device__ float g_GT[(size_t)B_ * D_ * D_];   // per-batch folded (Wo ∘ kv ∘ qnorm)
__device__ float g_qnorm[B_ * D_];
__device__ float g_kv[B_ * H_ * DH_ * DH_];

// =====================  helpers  ===========================================
__device__ __forceinline__ uint32_t smem_addr_u32(const void* p) {
    uint32_t a;
    asm("{ .reg .u64 t; cvta.to.shared.u64 t, %1; cvt.u32.u64 %0, t; }"
        : "=r"(a) : "l"(p));
    return a;
}

__device__ __forceinline__ uint32_t lds_b32(uint32_t a) {
    uint32_t v;
    asm volatile("ld.shared.b32 %0, [%1];" : "=r"(v) : "r"(a));
    return v;
}

__device__ __forceinline__ void sts_b64(uint32_t a, uint32_t x, uint32_t y) {
    asm volatile("st.shared.v2.b32 [%0], {%1, %2};" :: "r"(a), "r"(x), "r"(y) : "memory");
}

// fp32 pair -> packed bf16x2 hi and lo (x in low half)
__device__ __forceinline__ void split_pack(float x, float y, uint32_t& hi, uint32_t& lo) {
    __nv_bfloat162 h = __floats2bfloat162_rn(x, y);
    float hx = __bfloat162float(__low2bfloat16(h));
    float hy = __bfloat162float(__high2bfloat16(h));
    __nv_bfloat162 l = __floats2bfloat162_rn(x - hx, y - hy);
    hi = *reinterpret_cast<uint32_t*>(&h);
    lo = *reinterpret_cast<uint32_t*>(&l);
}

// classic warp MMA: D(16x8,f32) += A(16x16,bf16,row) * B(16x8,bf16,col)
__device__ __forceinline__ void mma16816(float* c, const uint32_t* a, const uint32_t* b) {
    asm volatile(
        "mma.sync.aligned.m16n8k16.row.col.f32.bf16.bf16.f32 "
        "{%0,%1,%2,%3}, {%4,%5,%6,%7}, {%8,%9}, {%0,%1,%2,%3};"
        : "+f"(c[0]), "+f"(c[1]), "+f"(c[2]), "+f"(c[3])
        : "r"(a[0]), "r"(a[1]), "r"(a[2]), "r"(a[3]), "r"(b[0]), "r"(b[1]));
}

// ---------------------------------------------------------------------------
// HMMA GEMM: C[M,1024] = A[M,1024] @ W[1024,1024]^T + bias (+epilogue)
// CTA 128x128, 8 warps (4M x 2N), warp tile 32x64, K-stage 32, double buffer.
// Split-bf16 3-product fp32 emulation.
//   MODE 0: plain        MODE 1: 1+elu      MODE 2: 1+elu, zero masked rows
//   MODE 3: plain, W is per-batch (W += (bm>>12)*1024*1024)
// Smem rows padded to 40 bf16 (80B): frag ld.shared.b32 banks (g*20+t)%32
// are all-distinct -> conflict-free.
// ---------------------------------------------------------------------------
#define AHI_ 0u
#define ALO_ 10240u
#define BHI_ 20480u
#define BLO_ 30720u
#define STG_ 40960u

template <int MODE>
__global__ void __launch_bounds__(256, 1)
gemm_hmma(const float* __restrict__ A, const float* __restrict__ Wbase,
          const float* __restrict__ bias, const int* __restrict__ mask,
          float* __restrict__ C)
{
    extern __shared__ __align__(16) char smem[];
    const uint32_t sb = smem_addr_u32(smem);

    const int tid   = threadIdx.x;
    const int lane  = tid & 31;
    const int wid   = tid >> 5;
    const int g     = lane >> 2;   // group id 0..7
    const int t     = lane & 3;    // thread-in-group
    const int warpM = wid & 3;     // 0..3  -> rows warpM*32
    const int warpN = wid >> 2;    // 0..1  -> cols warpN*64
    const int bm    = blockIdx.y << 7;
    const int bn    = blockIdx.x << 7;

    const float* W = Wbase;
    if (MODE == 3) W += ((size_t)(bm >> 12)) << 20;   // + b*1024*1024

    // global load mapping: thread covers rows r0+32i (i=0..3), float4 col c4
    const int r0 = tid >> 3;        // 0..31
    const int c4 = tid & 7;         // 0..7
    const float* Ap = A + (size_t)(bm + r0) * D_ + (c4 << 2);
    const float* Wp = W + (size_t)(bn + r0) * D_ + (c4 << 2);

    float acc[2][8][4];
#pragma unroll
    for (int mt = 0; mt < 2; mt++)
#pragma unroll
        for (int nt = 0; nt < 8; nt++)
#pragma unroll
            for (int r = 0; r < 4; r++) acc[mt][nt][r] = 0.f;

    float4 pa[4], pw[4];

    // frag base addresses (byte offsets into a stage)
    const uint32_t aoff = (uint32_t)((warpM * 32 + g) * 80 + (t << 2));
    const uint32_t boff = (uint32_t)((warpN * 64 + g) * 80 + (t << 2));
    const uint32_t soff = (uint32_t)((r0) * 80 + (c4 << 3));

    // ---- prologue: stage 0 ----
#pragma unroll
    for (int i = 0; i < 4; i++) {
        pa[i] = *(const float4*)(Ap + (size_t)(i << 5) * D_);
        pw[i] = *(const float4*)(Wp + (size_t)(i << 5) * D_);
    }
    {
        const uint32_t base = sb;
#pragma unroll
        for (int i = 0; i < 4; i++) {
            const uint32_t o = base + soff + (uint32_t)(i * 32 * 80);
            uint32_t h01, l01, h23, l23;
            split_pack(pa[i].x, pa[i].y, h01, l01);
            split_pack(pa[i].z, pa[i].w, h23, l23);
            sts_b64(o + AHI_, h01, h23);
            sts_b64(o + ALO_, l01, l23);
            split_pack(pw[i].x, pw[i].y, h01, l01);
            split_pack(pw[i].z, pw[i].w, h23, l23);
            sts_b64(o + BHI_, h01, h23);
            sts_b64(o + BLO_, l01, l23);
        }
    }
    __syncthreads();

#pragma unroll 1
    for (int s = 0; s < 32; ++s) {
        // prefetch next stage
        if (s < 31) {
            const int k0n = (s + 1) << 5;
#pragma unroll
            for (int i = 0; i < 4; i++) {
                pa[i] = *(const float4*)(Ap + k0n + (size_t)(i << 5) * D_);
                pw[i] = *(const float4*)(Wp + k0n + (size_t)(i << 5) * D_);
            }
        }

        // compute on current stage
        const uint32_t base = sb + (uint32_t)(s & 1) * STG_;
#pragma unroll
        for (int kk = 0; kk < 2; kk++) {
            const uint32_t kko = (uint32_t)(kk << 5);   // +32B per k16
            uint32_t ah[2][4], al[2][4];
#pragma unroll
            for (int mt = 0; mt < 2; mt++) {
                const uint32_t a0 = base + aoff + (uint32_t)(mt * 1280) + kko;
                ah[mt][0] = lds_b32(a0 + AHI_);
                ah[mt][1] = lds_b32(a0 + AHI_ + 640);
                ah[mt][2] = lds_b32(a0 + AHI_ + 16);
                ah[mt][3] = lds_b32(a0 + AHI_ + 656);
                al[mt][0] = lds_b32(a0 + ALO_);
                al[mt][1] = lds_b32(a0 + ALO_ + 640);
                al[mt][2] = lds_b32(a0 + ALO_ + 16);
                al[mt][3] = lds_b32(a0 + ALO_ + 656);
            }
#pragma unroll
            for (int nt = 0; nt < 8; nt++) {
                const uint32_t b0 = base + boff + (uint32_t)(nt * 640) + kko;
                uint32_t bh[2], bl[2];
                bh[0] = lds_b32(b0 + BHI_);
                bh[1] = lds_b32(b0 + BHI_ + 16);
                bl[0] = lds_b32(b0 + BLO_);
                bl[1] = lds_b32(b0 + BLO_ + 16);
#pragma unroll
                for (int mt = 0; mt < 2; mt++) {
                    mma16816(acc[mt][nt], ah[mt], bh);
                    mma16816(acc[mt][nt], ah[mt], bl);
                    mma16816(acc[mt][nt], al[mt], bh);
                }
            }
        }

        if (s < 31) {
            __syncthreads();
            const uint32_t nb = sb + (uint32_t)((s + 1) & 1) * STG_;
#pragma unroll
            for (int i = 0; i < 4; i++) {
                const uint32_t o = nb + soff + (uint32_t)(i * 32 * 80);
                uint32_t h01, l01, h23, l23;
                split_pack(pa[i].x, pa[i].y, h01, l01);
                split_pack(pa[i].z, pa[i].w, h23, l23);
                sts_b64(o + AHI_, h01, h23);
                sts_b64(o + ALO_, l01, l23);
                split_pack(pw[i].x, pw[i].y, h01, l01);
                split_pack(pw[i].z, pw[i].w, h23, l23);
                sts_b64(o + BHI_, h01, h23);
                sts_b64(o + BLO_, l01, l23);
            }
            __syncthreads();
        }
    }

    // ---- epilogue ----
#pragma unroll
    for (int mt = 0; mt < 2; mt++) {
        const int row0 = bm + warpM * 32 + mt * 16 + g;
        const int row1 = row0 + 8;
        int m0 = 0, m1 = 0;
        if (MODE == 2) { m0 = mask[row0]; m1 = mask[row1]; }
#pragma unroll
        for (int nt = 0; nt < 8; nt++) {
            const int col = bn + warpN * 64 + nt * 8 + (t << 1);
            const float2 bv = *(const float2*)(bias + col);
            float v0 = acc[mt][nt][0] + bv.x;
            float v1 = acc[mt][nt][1] + bv.y;
            float v2 = acc[mt][nt][2] + bv.x;
            float v3 = acc[mt][nt][3] + bv.y;
            if (MODE == 1 || MODE == 2) {
                v0 = (v0 > 0.f) ? (v0 + 1.f) : expf(v0);
                v1 = (v1 > 0.f) ? (v1 + 1.f) : expf(v1);
                v2 = (v2 > 0.f) ? (v2 + 1.f) : expf(v2);
                v3 = (v3 > 0.f) ? (v3 + 1.f) : expf(v3);
            }
            if (MODE == 2) {
                if (m0) { v0 = 0.f; v1 = 0.f; }
                if (m1) { v2 = 0.f; v3 = 0.f; }
            }
            *(float2*)(C + (size_t)row0 * D_ + col) = make_float2(v0, v1);
            *(float2*)(C + (size_t)row1 * D_ + col) = make_float2(v2, v3);
        }
    }
}

static constexpr size_t GEMM_SMEM = 2 * 40960;   // 80 KB

// ---------------------------------------------------------------------------
// q column sum-of-squares over sequence axis (atomics), on post-elu Q
// ---------------------------------------------------------------------------
__global__ void zero_qnorm_kernel()
{
    int i = blockIdx.x * 256 + threadIdx.x;
    if (i < B_ * D_) g_qnorm[i] = 0.f;
}

__global__ void __launch_bounds__(256) qcolsumsq_kernel()
{
    const int c  = blockIdx.x * 256 + threadIdx.x;
    const int b  = blockIdx.z;
    const int n0 = blockIdx.y * 256;
    const float* p = g_Q + ((size_t)(b * N_ + n0)) * D_ + c;
    float s = 0.f;
#pragma unroll 8
    for (int j = 0; j < 256; j++) {
        float v = p[(size_t)j * D_];
        s = fmaf(v, v, s);
    }
    atomicAdd(&g_qnorm[b * D_ + c], s);
}

// ---------------------------------------------------------------------------
// k row (feature-axis) L2 normalize, in place
// ---------------------------------------------------------------------------
__global__ void __launch_bounds__(256) knorm_kernel()
{
    const int row = blockIdx.x * 16 + (threadIdx.x >> 4);
    const int l   = threadIdx.x & 15;
    float* p = g_K + (size_t)row * DH_ + l * 4;
    float4 v = *(const float4*)p;
    float s = v.x * v.x + v.y * v.y + v.z * v.z + v.w * v.w;
    s += __shfl_xor_sync(0xffffffffu, s, 1);
    s += __shfl_xor_sync(0xffffffffu, s, 2);
    s += __shfl_xor_sync(0xffffffffu, s, 4);
    s += __shfl_xor_sync(0xffffffffu, s, 8);
    const float inv = 1.0f / fmaxf(sqrtf(s), 1e-12f);
    v.x *= inv; v.y *= inv; v.z *= inv; v.w *= inv;
    *(float4*)p = v;
}

// ---------------------------------------------------------------------------
// kv[b,h,d,e] = sum_n k[b,n,h*64+d] * v[b,n,h*64+e]
// ---------------------------------------------------------------------------
__global__ void __launch_bounds__(256) kv_kernel()
{
    __shared__ __align__(16) float Ks[64][64];
    __shared__ __align__(16) float Vs[64][64];
    const int tid = threadIdx.x;
    const int bh  = blockIdx.x;
    const int b   = bh >> 4, h = bh & 15;
    const size_t base = (size_t)b * N_ * D_ + (size_t)h * DH_;
    const int d0 = (tid & 15) << 2;
    const int e0 = (tid >> 4) << 2;

    float acc[4][4];
#pragma unroll
    for (int i = 0; i < 4; i++)
#pragma unroll
        for (int j = 0; j < 4; j++) acc[i][j] = 0.f;

    for (int n0 = 0; n0 < N_; n0 += 64) {
        __syncthreads();
#pragma unroll
        for (int it = 0; it < 4; it++) {
            int rj = (it << 4) + (tid >> 4);
            int q  = (tid & 15) << 2;
            size_t gidx = base + (size_t)(n0 + rj) * D_ + q;
            *(float4*)&Ks[rj][q] = *(const float4*)(g_K + gidx);
            *(float4*)&Vs[rj][q] = *(const float4*)(g_V + gidx);
        }
        __syncthreads();
#pragma unroll 8
        for (int j = 0; j < 64; j++) {
            float4 kd = *(const float4*)&Ks[j][d0];
            float4 ve = *(const float4*)&Vs[j][e0];
            float kda[4] = {kd.x, kd.y, kd.z, kd.w};
            float vea[4] = {ve.x, ve.y, ve.z, ve.w};
#pragma unroll
            for (int di = 0; di < 4; di++)
#pragma unroll
                for (int ei = 0; ei < 4; ei++)
                    acc[di][ei] = fmaf(kda[di], vea[ei], acc[di][ei]);
        }
    }

    float* outp = g_kv + (size_t)bh * (DH_ * DH_);
#pragma unroll
    for (int di = 0; di < 4; di++)
        *(float4*)&outp[(d0 + di) * DH_ + e0] =
            make_float4(acc[di][0], acc[di][1], acc[di][2], acc[di][3]);
}

// ---------------------------------------------------------------------------
// GT_b[j][h*64+d] = (sum_e kv[b,h][d][e] * Wo[j][h*64+e]) / max(sqrt(qn),eps)
// so that  out = Q_raw @ GT_b^T + bo.   Tiny: 1 GFLOP total.
// ---------------------------------------------------------------------------
__global__ void __launch_bounds__(256) gt_kernel(const float* __restrict__ Wo)
{
    __shared__ __align__(16) float kvs[64][65];
    __shared__ __align__(16) float Wos[64][65];
    const int tid = threadIdx.x;
    const int jt = blockIdx.x, h = blockIdx.y, b = blockIdx.z;
    const float* kvp = g_kv + (size_t)(b * H_ + h) * (DH_ * DH_);

#pragma unroll
    for (int i = 0; i < 16; i++) {
        const int idx = tid + (i << 8);
        const int r = idx >> 6, e = idx & 63;
        kvs[r][e] = kvp[idx];
        Wos[r][e] = Wo[(size_t)(jt * 64 + r) * D_ + h * 64 + e];
    }
    __syncthreads();

    const int tj = (tid >> 4) << 2;   // 4 j rows
    const int td = (tid & 15) << 2;   // 4 d cols
    float acc[4][4];
#pragma unroll
    for (int i = 0; i < 4; i++)
#pragma unroll
        for (int j = 0; j < 4; j++) acc[i][j] = 0.f;

#pragma unroll 16
    for (int e = 0; e < 64; e++) {
        float wv[4], kvv[4];
#pragma unroll
        for (int i = 0; i < 4; i++) { wv[i] = Wos[tj + i][e]; kvv[i] = kvs[td + i][e]; }
#pragma unroll
        for (int i = 0; i < 4; i++)
#pragma unroll
            for (int j = 0; j < 4; j++)
                acc[i][j] = fmaf(wv[i], kvv[j], acc[i][j]);
    }

    float sc[4];
#pragma unroll
    for (int j = 0; j < 4; j++)
        sc[j] = 1.0f / fmaxf(sqrtf(g_qnorm[b * D_ + h * 64 + td + j]), 1e-12f);

    float* outp = g_GT + ((size_t)b << 20) + (size_t)(jt * 64 + tj) * D_ + h * 64 + td;
#pragma unroll
    for (int i = 0; i < 4; i++)
        *(float4*)(outp + (size_t)i * D_) =
            make_float4(acc[i][0] * sc[0], acc[i][1] * sc[1],
                        acc[i][2] * sc[2], acc[i][3] * sc[3]);
}

// ---------------------------------------------------------------------------
extern "C" void kernel_launch(void* const* d_in, const int* in_sizes, int n_in,
                              void* d_out, int out_size)
{
    (void)in_sizes; (void)n_in; (void)out_size;
    const float* query = (const float*)d_in[0];
    const float* key   = (const float*)d_in[1];
    const float* value = (const float*)d_in[2];
    const int*   mask  = (const int*)d_in[3];   // bool materialized as int32
    const float* Wq = (const float*)d_in[4];
    const float* bq = (const float*)d_in[5];
    const float* Wk = (const float*)d_in[6];
    const float* bk = (const float*)d_in[7];
    const float* Wv = (const float*)d_in[8];
    const float* bv = (const float*)d_in[9];
    const float* Wo = (const float*)d_in[10];
    const float* bo = (const float*)d_in[11];
    float* out = (float*)d_out;

    float *Q = nullptr, *K = nullptr, *V = nullptr, *GT = nullptr;
    cudaGetSymbolAddress((void**)&Q, g_Q);
    cudaGetSymbolAddress((void**)&K, g_K);
    cudaGetSymbolAddress((void**)&V, g_V);
    cudaGetSymbolAddress((void**)&GT, g_GT);

    cudaFuncSetAttribute(gemm_hmma<0>, cudaFuncAttributeMaxDynamicSharedMemorySize, GEMM_SMEM);
    cudaFuncSetAttribute(gemm_hmma<1>, cudaFuncAttributeMaxDynamicSharedMemorySize, GEMM_SMEM);
    cudaFuncSetAttribute(gemm_hmma<2>, cudaFuncAttributeMaxDynamicSharedMemorySize, GEMM_SMEM);
    cudaFuncSetAttribute(gemm_hmma<3>, cudaFuncAttributeMaxDynamicSharedMemorySize, GEMM_SMEM);

    dim3 gblk(256);
    dim3 ggrid(D_ / 128, M_ / 128);   // (8, 256)

    gemm_hmma<1><<<ggrid, gblk, GEMM_SMEM>>>(query, Wq, bq, nullptr, Q);
    gemm_hmma<2><<<ggrid, gblk, GEMM_SMEM>>>(key,   Wk, bk, mask,    K);
    gemm_hmma<0><<<ggrid, gblk, GEMM_SMEM>>>(value, Wv, bv, nullptr, V);

    zero_qnorm_kernel<<<(B_ * D_ + 255) / 256, 256>>>();
    qcolsumsq_kernel<<<dim3(4, 16, 8), 256>>>();
    knorm_kernel<<<(M_ * H_) / 16, 256>>>();

    kv_kernel<<<B_ * H_, 256>>>();
    gt_kernel<<<dim3(16, 16, 8), 256>>>(Wo);

    gemm_hmma<3><<<ggrid, gblk, GEMM_SMEM>>>(Q, GT, bo, nullptr, out);
}